// round 16
// baseline (speedup 1.0000x reference)
#include <cuda_runtime.h>
#include <cuda_bf16.h>
#include <cuda_fp16.h>
#include <cstdint>
#include <math.h>

// ---------------- problem shape ----------------
#define B_SZ 16384
#define C_SZ 4096
#define D_SZ 256
// logical K = 512 : A = [z^2 | z],  W = [iv | -2*mu*iv]
// a*w = hi_a*hi_w + lo_a*hi_w + hi_a*lo_w  (all fp16 operands, fp32 accum)

// ---------------- GEMM tile ----------------
#define BM 128
#define BN 128
#define NKT 16             // k-tiles of 32
#define NTHREADS 128       // 4 warps, each owns a 64x64 output tile
#define NTILES 4096
#define GRID_P 304         // persistent CTAs (2/SM on 152-SM GB300)

#define A_TILE_U4 1024     // 512 hi + 512 lo fp16 -> 16KB
#define W_TILE_U4 1024
#define STAGE_U4 (A_TILE_U4 + W_TILE_U4)            // 2048 -> 32KB
#define STAGE_BYTES (STAGE_U4 * 16)
#define NSTAGES 2
#define SMEM_BYTES (NSTAGES * STAGE_BYTES)          // 65536 -> 2 CTAs/SM

// -------- scratch (__device__ globals; no allocation allowed) --------
__device__ uint4 g_A[(size_t)128 * NKT * A_TILE_U4];  // 32 MB
__device__ uint4 g_W[(size_t)32 * NKT * W_TILE_U4];   // 8 MB
__device__ float g_constc[C_SZ];                      // folded: -0.5*const_c + OFF
// fusion control (reset by prep each launch)
__device__ int g_done_[128];     // GEMM tiles completed per row-group
__device__ int g_rowin_[128];    // softmax rows claimed per row-group
__device__ int g_grpcur_;        // lower bound of non-exhausted group

// ---------------- helpers ----------------
#define FP16_MIN_NORMAL 6.104e-5f

__device__ __forceinline__ float fp16_hi(float x) {
    if (fabsf(x) < FP16_MIN_NORMAL) return 0.0f;
    return __half2float(__float2half_rn(x));
}
__device__ __forceinline__ uint32_t pack_h2_hi(float e, float o) {
    __half2 t;
    t.x = (fabsf(e) < FP16_MIN_NORMAL) ? __half(0.0f) : __float2half_rn(e);
    t.y = (fabsf(o) < FP16_MIN_NORMAL) ? __half(0.0f) : __float2half_rn(o);
    return *(uint32_t*)&t;
}
__device__ __forceinline__ uint32_t pack_h2_raw(float e, float o) {
    __half2 t = __floats2half2_rn(e, o);
    return *(uint32_t*)&t;
}
__device__ __forceinline__ uint32_t smem_u32(const void* p) {
    uint32_t a;
    asm("{ .reg .u64 t; cvta.to.shared.u64 t, %1; cvt.u32.u64 %0, t; }" : "=r"(a) : "l"(p));
    return a;
}
__device__ __forceinline__ void cp16(uint32_t dst, const void* src) {
    asm volatile("cp.async.cg.shared.global [%0], [%1], 16;" :: "r"(dst), "l"(src));
}
#define CP_COMMIT() asm volatile("cp.async.commit_group;" ::: "memory")
#define CP_WAIT1()  asm volatile("cp.async.wait_group 1;" ::: "memory")
#define CP_WAIT0()  asm volatile("cp.async.wait_group 0;" ::: "memory")

__device__ __forceinline__ void mma_f16(float* d, const uint4& a, uint32_t b0, uint32_t b1) {
    asm volatile(
        "mma.sync.aligned.m16n8k16.row.col.f32.f16.f16.f32 "
        "{%0,%1,%2,%3}, {%4,%5,%6,%7}, {%8,%9}, {%0,%1,%2,%3};"
        : "+f"(d[0]), "+f"(d[1]), "+f"(d[2]), "+f"(d[3])
        : "r"(a.x), "r"(a.y), "r"(a.z), "r"(a.w), "r"(b0), "r"(b1));
}

// logical operand values
__device__ __forceinline__ float Aval(const float* __restrict__ z, int r, int k) {
    float v = __ldg(z + (size_t)r * D_SZ + (k & 255));
    return (k < 256) ? v * v : v;
}
__device__ __forceinline__ float Wval(const float* __restrict__ mu,
                                      const float* __restrict__ lv, int c, int k) {
    int d = k & 255;
    float l = __ldg(lv + (size_t)c * D_SZ + d);
    float iv = expf(-l);
    return (k < 256) ? iv : -2.0f * __ldg(mu + (size_t)c * D_SZ + d) * iv;
}

// ---------------- ONE fused prep kernel (+ control reset) ----------------
#define PREP_A_BLOCKS 4096
#define PREP_W_BLOCKS 1024
#define PREP_C_BLOCKS 4096
#define PREP_BLOCKS (PREP_A_BLOCKS + PREP_W_BLOCKS + PREP_C_BLOCKS + 1)

__global__ void __launch_bounds__(256)
prep_all_kernel(const float* __restrict__ z,
                const float* __restrict__ mu,
                const float* __restrict__ logvar) {
    int blk = blockIdx.x;

    if (blk < PREP_A_BLOCKS) {
        int idx = blk * 256 + threadIdx.x;             // 1,048,576
        int lane = idx & 31, ks = (idx >> 5) & 1, mb = (idx >> 6) & 7;
        int kt = (idx >> 9) & 15, mt = idx >> 13;
        int grp = lane >> 2, tig = lane & 3;
        int r0 = mt * BM + mb * 16 + grp;
        int kbase = kt * 32 + ks * 16;
        int ke0 = kbase + tig * 2, ke1 = kbase + 8 + tig * 2;

        float a00 = Aval(z, r0, ke0),     a01 = Aval(z, r0, ke0 + 1);
        float a10 = Aval(z, r0 + 8, ke0), a11 = Aval(z, r0 + 8, ke0 + 1);
        float a20 = Aval(z, r0, ke1),     a21 = Aval(z, r0, ke1 + 1);
        float a30 = Aval(z, r0 + 8, ke1), a31 = Aval(z, r0 + 8, ke1 + 1);

        uint4 hi, lo;
        hi.x = pack_h2_hi(a00, a01); hi.y = pack_h2_hi(a10, a11);
        hi.z = pack_h2_hi(a20, a21); hi.w = pack_h2_hi(a30, a31);
        lo.x = pack_h2_raw(a00 - fp16_hi(a00), a01 - fp16_hi(a01));
        lo.y = pack_h2_raw(a10 - fp16_hi(a10), a11 - fp16_hi(a11));
        lo.z = pack_h2_raw(a20 - fp16_hi(a20), a21 - fp16_hi(a21));
        lo.w = pack_h2_raw(a30 - fp16_hi(a30), a31 - fp16_hi(a31));

        size_t base = (size_t)(mt * NKT + kt) * A_TILE_U4;
        g_A[base + (mb * 2 + ks) * 32 + lane] = hi;
        g_A[base + 512 + (mb * 2 + ks) * 32 + lane] = lo;

    } else if (blk < PREP_A_BLOCKS + PREP_W_BLOCKS) {
        int idx = (blk - PREP_A_BLOCKS) * 256 + threadIdx.x;   // 262,144
        int lane = idx & 31, ks = (idx >> 5) & 1, nbp = (idx >> 6) & 7;
        int kt = (idx >> 9) & 15, nt = idx >> 13;
        int grp = lane >> 2, tig = lane & 3;
        int c0 = nt * 128 + nbp * 16 + grp;
        int c1 = c0 + 8;
        int kbase = kt * 32 + ks * 16;
        int ke0 = kbase + tig * 2, ke1 = kbase + 8 + tig * 2;

        float w00 = Wval(mu, logvar, c0, ke0), w01 = Wval(mu, logvar, c0, ke0 + 1);
        float w10 = Wval(mu, logvar, c0, ke1), w11 = Wval(mu, logvar, c0, ke1 + 1);
        float w20 = Wval(mu, logvar, c1, ke0), w21 = Wval(mu, logvar, c1, ke0 + 1);
        float w30 = Wval(mu, logvar, c1, ke1), w31 = Wval(mu, logvar, c1, ke1 + 1);

        uint4 hi, lo;
        hi.x = pack_h2_hi(w00, w01); hi.y = pack_h2_hi(w10, w11);
        hi.z = pack_h2_hi(w20, w21); hi.w = pack_h2_hi(w30, w31);
        lo.x = pack_h2_raw(w00 - fp16_hi(w00), w01 - fp16_hi(w01));
        lo.y = pack_h2_raw(w10 - fp16_hi(w10), w11 - fp16_hi(w11));
        lo.z = pack_h2_raw(w20 - fp16_hi(w20), w21 - fp16_hi(w21));
        lo.w = pack_h2_raw(w30 - fp16_hi(w30), w31 - fp16_hi(w31));

        size_t base = (size_t)(nt * NKT + kt) * W_TILE_U4;
        g_W[base + (nbp * 2 + ks) * 32 + lane] = hi;
        g_W[base + 512 + (nbp * 2 + ks) * 32 + lane] = lo;

    } else if (blk < PREP_A_BLOCKS + PREP_W_BLOCKS + PREP_C_BLOCKS) {
        int c = blk - PREP_A_BLOCKS - PREP_W_BLOCKS;
        int d = threadIdx.x;
        float lv = logvar[(size_t)c * D_SZ + d];
        float m  = mu[(size_t)c * D_SZ + d];
        float iv = expf(-lv);
        __shared__ float red[256];
        red[d] = fmaf(m * m, iv, lv);
        __syncthreads();
        #pragma unroll
        for (int s = 128; s > 0; s >>= 1) {
            if (d < s) red[d] += red[d + s];
            __syncthreads();
        }
        if (d == 0) {
            const float OFF = -235.24826450039622f - 8.317766166719343f;
            g_constc[c] = fmaf(-0.5f, red[0], OFF);   // folded
        }
    } else {
        // control reset (runs every launch, before GEMM via stream order)
        int d = threadIdx.x;
        if (d < 128) { g_done_[d] = 0; g_rowin_[d] = 0; }
        if (d == 0) g_grpcur_ = 0;
    }
}

// ---------------- softmax work pop (single thread) ----------------
// returns row id >=0, -1 = none ready now, -2 = all claimed
__device__ __forceinline__ int try_pop() {
    int g = *(volatile int*)&g_grpcur_;
    while (g < 128) {
        if (*(volatile int*)&g_done_[g] < 32) return -1;
        int r = atomicAdd(&g_rowin_[g], 1);
        if (r < 128) return (g << 7) + r;
        if (r == 128) atomicMax(&g_grpcur_, g + 1);
        g++;
    }
    return -2;
}

// ---------------- fused GEMM + softmax (persistent) ----------------
__global__ void __launch_bounds__(NTHREADS, 2)
gemm_fused_kernel(float* __restrict__ out) {
    extern __shared__ uint4 smem4[];
    __shared__ int sPop;
    const int tid = threadIdx.x;
    const int lane = tid & 31;
    const int wid = tid >> 5;        // 0..3
    const int wm = wid >> 1;
    const int wn = wid & 1;
    const int grp = lane >> 2;
    const int tig = lane & 3;
    const uint32_t sb = smem_u32(smem4);

    float* logits = out;
    float* probs  = out + (size_t)B_SZ * C_SZ;
    float* pred   = out + (size_t)2 * B_SZ * C_SZ;

    // softmax row processor (all 128 threads; uses stage smem as scratch)
    #define PROCESS_ROW(rr)                                                     \
    {                                                                           \
        float* row = (float*)smem4;                                             \
        float* sm_ = row + C_SZ;                                                \
        int*   si_ = (int*)(sm_ + 128);                                         \
        float* ss_ = (float*)(si_ + 128);                                       \
        __threadfence();                                                        \
        const float4* src_ = (const float4*)(logits + (size_t)(rr) * C_SZ);     \
        _Pragma("unroll")                                                       \
        for (int k = 0; k < 8; k++) {                                           \
            int i = k * 128 + tid;                                              \
            ((float4*)row)[i] = __ldcg(src_ + i);                               \
        }                                                                       \
        __syncthreads();                                                        \
        float m_ = -INFINITY; int mi_ = 0;                                      \
        _Pragma("unroll")                                                       \
        for (int k = 0; k < 32; k++) {                                          \
            int c = k * 128 + tid;                                              \
            float v = row[c];                                                   \
            if (v > m_) { m_ = v; mi_ = c; }                                    \
        }                                                                       \
        sm_[tid] = m_; si_[tid] = mi_;                                          \
        __syncthreads();                                                        \
        _Pragma("unroll")                                                       \
        for (int s = 64; s > 0; s >>= 1) {                                      \
            if (tid < s) {                                                      \
                if (sm_[tid + s] > sm_[tid] ||                                  \
                    (sm_[tid + s] == sm_[tid] && si_[tid + s] < si_[tid])) {    \
                    sm_[tid] = sm_[tid + s]; si_[tid] = si_[tid + s];           \
                }                                                               \
            }                                                                   \
            __syncthreads();                                                    \
        }                                                                       \
        const float rmax_ = sm_[0];                                             \
        const int amax_ = si_[0];                                               \
        __syncthreads();                                                        \
        float s_ = 0.0f;                                                        \
        _Pragma("unroll")                                                       \
        for (int k = 0; k < 32; k++) {                                          \
            int c = k * 128 + tid;                                              \
            float e = __expf(row[c] - rmax_);                                   \
            row[c] = e;                                                         \
            s_ += e;                                                            \
        }                                                                       \
        ss_[tid] = s_;                                                          \
        __syncthreads();                                                        \
        _Pragma("unroll")                                                       \
        for (int st = 64; st > 0; st >>= 1) {                                   \
            if (tid < st) ss_[tid] += ss_[tid + st];                            \
            __syncthreads();                                                    \
        }                                                                       \
        const float inv_ = 1.0f / ss_[0];                                       \
        float4* dst_ = (float4*)(probs + (size_t)(rr) * C_SZ);                  \
        _Pragma("unroll")                                                       \
        for (int k = 0; k < 8; k++) {                                           \
            int i = k * 128 + tid;                                              \
            float4 e4 = ((const float4*)row)[i];                                \
            e4.x *= inv_; e4.y *= inv_; e4.z *= inv_; e4.w *= inv_;             \
            __stcs(dst_ + i, e4);                                               \
        }                                                                       \
        if (tid == 0) pred[rr] = (float)amax_;                                  \
        __syncthreads();                                                        \
    }

    #define LOAD_STAGE(slot, AB, WB, kt)                                        \
    {                                                                           \
        uint32_t s0 = sb + (uint32_t)(slot) * STAGE_BYTES;                      \
        const uint4* ag = (AB) + (size_t)(kt) * A_TILE_U4;                      \
        _Pragma("unroll")                                                       \
        for (int c = 0; c < 8; c++) {                                           \
            int id = tid + c * NTHREADS;                                        \
            cp16(s0 + (uint32_t)id * 16, ag + id);                              \
        }                                                                       \
        const uint4* wg = (WB) + (size_t)(kt) * W_TILE_U4;                      \
        uint32_t s1 = s0 + A_TILE_U4 * 16;                                      \
        _Pragma("unroll")                                                       \
        for (int c = 0; c < 8; c++) {                                           \
            int id = tid + c * NTHREADS;                                        \
            cp16(s1 + (uint32_t)id * 16, wg + id);                              \
        }                                                                       \
    }

    for (int t = blockIdx.x; t < NTILES; t += GRID_P) {
        const int mt = t >> 5, nt = t & 31;
        const uint4* Ab = g_A + (size_t)mt * NKT * A_TILE_U4;
        const uint4* Wb = g_W + (size_t)nt * NKT * W_TILE_U4;

        float acc[4][8][4];
        #pragma unroll
        for (int i = 0; i < 4; i++)
            #pragma unroll
            for (int j = 0; j < 8; j++)
                #pragma unroll
                for (int q = 0; q < 4; q++) acc[i][j][q] = 0.0f;

        LOAD_STAGE(0, Ab, Wb, 0) CP_COMMIT();
        LOAD_STAGE(1, Ab, Wb, 1) CP_COMMIT();

        #pragma unroll
        for (int kt = 0; kt < NKT; kt++) {
            const int slot = kt & 1;
            if (kt == NKT - 1) { CP_WAIT0(); } else { CP_WAIT1(); }
            __syncthreads();

            const uint4* S   = smem4 + slot * STAGE_U4;
            const uint4* Ahi = S;
            const uint4* Alo = S + 512;
            const uint4* Whi = S + A_TILE_U4;
            const uint4* Wlo = S + A_TILE_U4 + 512;

            #pragma unroll
            for (int s = 0; s < 2; s++) {
                uint4 ah[4], al[4], wh[4], wl[4];
                #pragma unroll
                for (int mf = 0; mf < 4; mf++) {
                    ah[mf] = Ahi[((wm * 4 + mf) * 2 + s) * 32 + lane];
                    al[mf] = Alo[((wm * 4 + mf) * 2 + s) * 32 + lane];
                }
                #pragma unroll
                for (int p = 0; p < 4; p++) {
                    wh[p] = Whi[((wn * 4 + p) * 2 + s) * 32 + lane];
                    wl[p] = Wlo[((wn * 4 + p) * 2 + s) * 32 + lane];
                }
                #pragma unroll
                for (int mf = 0; mf < 4; mf++)
                    #pragma unroll
                    for (int p = 0; p < 4; p++) {
                        mma_f16(acc[mf][2 * p],     ah[mf], wh[p].x, wh[p].y);
                        mma_f16(acc[mf][2 * p + 1], ah[mf], wh[p].z, wh[p].w);
                    }
                #pragma unroll
                for (int mf = 0; mf < 4; mf++)
                    #pragma unroll
                    for (int p = 0; p < 4; p++) {
                        mma_f16(acc[mf][2 * p],     al[mf], wh[p].x, wh[p].y);
                        mma_f16(acc[mf][2 * p + 1], al[mf], wh[p].z, wh[p].w);
                    }
                #pragma unroll
                for (int mf = 0; mf < 4; mf++)
                    #pragma unroll
                    for (int p = 0; p < 4; p++) {
                        mma_f16(acc[mf][2 * p],     ah[mf], wl[p].x, wl[p].y);
                        mma_f16(acc[mf][2 * p + 1], ah[mf], wl[p].z, wl[p].w);
                    }
            }

            __syncthreads();
            if (kt + 2 < NKT) {
                LOAD_STAGE(slot, Ab, Wb, kt + 2)
                CP_COMMIT();
            }
        }

        // epilogue
        const int m0 = mt * BM, n0 = nt * BN;
        #pragma unroll
        for (int mf = 0; mf < 4; mf++) {
            #pragma unroll
            for (int g = 0; g < 8; g++) {
                int row = m0 + wm * 64 + mf * 16 + grp;
                int col = n0 + wn * 64 + g * 8 + tig * 2;
                float c0 = __ldg(g_constc + col);
                float c1 = __ldg(g_constc + col + 1);
                float2 o0, o1;
                o0.x = fmaf(-0.5f, acc[mf][g][0], c0);
                o0.y = fmaf(-0.5f, acc[mf][g][1], c1);
                o1.x = fmaf(-0.5f, acc[mf][g][2], c0);
                o1.y = fmaf(-0.5f, acc[mf][g][3], c1);
                *(float2*)(logits + (size_t)row * C_SZ + col)       = o0;
                *(float2*)(logits + (size_t)(row + 8) * C_SZ + col) = o1;
            }
        }
        __threadfence();              // this thread's logits visible
        __syncthreads();              // all threads fenced
        if (tid == 0) {
            atomicAdd(&g_done_[mt], 1);
            sPop = 0;
        }
        __syncthreads();

        // drain up to 6 ready softmax rows (no spinning in GEMM phase)
        #pragma unroll 1
        for (int cap = 0; cap < 6; cap++) {
            if (tid == 0) sPop = try_pop();
            __syncthreads();
            int r = sPop;
            if (r < 0) break;
            PROCESS_ROW(r)
        }
    }

    // tail: drain everything remaining (own GEMM done; spin-safe)
    #pragma unroll 1
    while (true) {
        if (tid == 0) {
            int v = try_pop();
            while (v == -1) { __nanosleep(256); v = try_pop(); }
            sPop = v;
        }
        __syncthreads();
        int r = sPop;
        if (r < 0) break;             // -2: all rows claimed
        PROCESS_ROW(r)
    }
}

// ---------------- launch ----------------
extern "C" void kernel_launch(void* const* d_in, const int* in_sizes, int n_in,
                              void* d_out, int out_size) {
    const float* z      = (const float*)d_in[0];
    const float* mu     = (const float*)d_in[1];
    const float* logvar = (const float*)d_in[2];
    float* out = (float*)d_out;

    cudaFuncSetAttribute(gemm_fused_kernel,
                         cudaFuncAttributeMaxDynamicSharedMemorySize, SMEM_BYTES);

    prep_all_kernel<<<PREP_BLOCKS, 256>>>(z, mu, logvar);
    gemm_fused_kernel<<<GRID_P, NTHREADS, SMEM_BYTES>>>(out);
}

// round 17
// speedup vs baseline: 1.4994x; 1.4994x over previous
#include <cuda_runtime.h>
#include <cuda_bf16.h>
#include <cuda_fp16.h>
#include <cstdint>
#include <math.h>

// ---------------- problem shape ----------------
#define B_SZ 16384
#define C_SZ 4096
#define D_SZ 256
// logical K = 512 : A = [z^2 | z],  W = [iv | -2*mu*iv]
// a*w = hi_a*hi_w + lo_a*hi_w + hi_a*lo_w  (all fp16 operands, fp32 accum)

// ---------------- GEMM tile ----------------
#define BM 128
#define BN 128
#define NKT 16             // k-tiles of 32
#define NTHREADS 128       // 4 warps, each owns a 64x64 output tile

#define A_TILE_U4 1024     // 512 hi + 512 lo fp16 -> 16KB
#define W_TILE_U4 1024
#define STAGE_U4 (A_TILE_U4 + W_TILE_U4)            // 2048 -> 32KB
#define STAGE_BYTES (STAGE_U4 * 16)
#define NSTAGES 2
#define SMEM_BYTES (NSTAGES * STAGE_BYTES)          // 65536 -> 2 CTAs/SM

// -------- scratch (__device__ globals; no allocation allowed) --------
__device__ uint4 g_A[(size_t)128 * NKT * A_TILE_U4];  // 32 MB
__device__ uint4 g_W[(size_t)32 * NKT * W_TILE_U4];   // 8 MB
__device__ float g_constc[C_SZ];                      // folded: -0.5*const_c + OFF

// ---------------- helpers ----------------
#define FP16_MIN_NORMAL 6.104e-5f

__device__ __forceinline__ float fp16_hi(float x) {
    if (fabsf(x) < FP16_MIN_NORMAL) return 0.0f;     // keep hi NORMAL fp16 (or 0)
    return __half2float(__float2half_rn(x));
}
__device__ __forceinline__ uint32_t pack_h2_hi(float e, float o) {
    __half2 t;
    t.x = (fabsf(e) < FP16_MIN_NORMAL) ? __half(0.0f) : __float2half_rn(e);
    t.y = (fabsf(o) < FP16_MIN_NORMAL) ? __half(0.0f) : __float2half_rn(o);
    return *(uint32_t*)&t;
}
__device__ __forceinline__ uint32_t pack_h2_raw(float e, float o) {
    __half2 t = __floats2half2_rn(e, o);
    return *(uint32_t*)&t;
}
__device__ __forceinline__ uint32_t smem_u32(const void* p) {
    uint32_t a;
    asm("{ .reg .u64 t; cvta.to.shared.u64 t, %1; cvt.u32.u64 %0, t; }" : "=r"(a) : "l"(p));
    return a;
}
__device__ __forceinline__ void cp16(uint32_t dst, const void* src) {
    asm volatile("cp.async.cg.shared.global [%0], [%1], 16;" :: "r"(dst), "l"(src));
}
#define CP_COMMIT() asm volatile("cp.async.commit_group;" ::: "memory")
#define CP_WAIT1()  asm volatile("cp.async.wait_group 1;" ::: "memory")
#define CP_WAIT0()  asm volatile("cp.async.wait_group 0;" ::: "memory")

__device__ __forceinline__ void mma_f16(float* d, const uint4& a, uint32_t b0, uint32_t b1) {
    asm volatile(
        "mma.sync.aligned.m16n8k16.row.col.f32.f16.f16.f32 "
        "{%0,%1,%2,%3}, {%4,%5,%6,%7}, {%8,%9}, {%0,%1,%2,%3};"
        : "+f"(d[0]), "+f"(d[1]), "+f"(d[2]), "+f"(d[3])
        : "r"(a.x), "r"(a.y), "r"(a.z), "r"(a.w), "r"(b0), "r"(b1));
}

// logical operand values
__device__ __forceinline__ float Aval(const float* __restrict__ z, int r, int k) {
    float v = __ldg(z + (size_t)r * D_SZ + (k & 255));
    return (k < 256) ? v * v : v;
}
__device__ __forceinline__ float Wval(const float* __restrict__ mu,
                                      const float* __restrict__ lv, int c, int k) {
    int d = k & 255;
    float l = __ldg(lv + (size_t)c * D_SZ + d);
    float iv = expf(-l);
    return (k < 256) ? iv : -2.0f * __ldg(mu + (size_t)c * D_SZ + d) * iv;
}

// ---------------- ONE fused prep kernel ----------------
#define PREP_A_BLOCKS 4096
#define PREP_W_BLOCKS 1024
#define PREP_C_BLOCKS 4096
#define PREP_BLOCKS (PREP_A_BLOCKS + PREP_W_BLOCKS + PREP_C_BLOCKS)

__global__ void __launch_bounds__(256)
prep_all_kernel(const float* __restrict__ z,
                const float* __restrict__ mu,
                const float* __restrict__ logvar) {
    int blk = blockIdx.x;

    if (blk < PREP_A_BLOCKS) {
        // A fragments: fields lane[0:5) ks[5:6) mb[6:9) kt[9:13) mt[13:)
        int idx = blk * 256 + threadIdx.x;             // 1,048,576
        int lane = idx & 31, ks = (idx >> 5) & 1, mb = (idx >> 6) & 7;
        int kt = (idx >> 9) & 15, mt = idx >> 13;
        int grp = lane >> 2, tig = lane & 3;
        int r0 = mt * BM + mb * 16 + grp;
        int kbase = kt * 32 + ks * 16;
        int ke0 = kbase + tig * 2, ke1 = kbase + 8 + tig * 2;

        float a00 = Aval(z, r0, ke0),     a01 = Aval(z, r0, ke0 + 1);
        float a10 = Aval(z, r0 + 8, ke0), a11 = Aval(z, r0 + 8, ke0 + 1);
        float a20 = Aval(z, r0, ke1),     a21 = Aval(z, r0, ke1 + 1);
        float a30 = Aval(z, r0 + 8, ke1), a31 = Aval(z, r0 + 8, ke1 + 1);

        uint4 hi, lo;
        hi.x = pack_h2_hi(a00, a01); hi.y = pack_h2_hi(a10, a11);
        hi.z = pack_h2_hi(a20, a21); hi.w = pack_h2_hi(a30, a31);
        lo.x = pack_h2_raw(a00 - fp16_hi(a00), a01 - fp16_hi(a01));
        lo.y = pack_h2_raw(a10 - fp16_hi(a10), a11 - fp16_hi(a11));
        lo.z = pack_h2_raw(a20 - fp16_hi(a20), a21 - fp16_hi(a21));
        lo.w = pack_h2_raw(a30 - fp16_hi(a30), a31 - fp16_hi(a31));

        size_t base = (size_t)(mt * NKT + kt) * A_TILE_U4;
        g_A[base + (mb * 2 + ks) * 32 + lane] = hi;
        g_A[base + 512 + (mb * 2 + ks) * 32 + lane] = lo;

    } else if (blk < PREP_A_BLOCKS + PREP_W_BLOCKS) {
        // W fragments: fields lane[0:5) ks[5:6) nbp[6:9) kt[9:13) nt[13:)
        int idx = (blk - PREP_A_BLOCKS) * 256 + threadIdx.x;   // 262,144
        int lane = idx & 31, ks = (idx >> 5) & 1, nbp = (idx >> 6) & 7;
        int kt = (idx >> 9) & 15, nt = idx >> 13;
        int grp = lane >> 2, tig = lane & 3;
        int c0 = nt * 128 + nbp * 16 + grp;
        int c1 = c0 + 8;
        int kbase = kt * 32 + ks * 16;
        int ke0 = kbase + tig * 2, ke1 = kbase + 8 + tig * 2;

        float w00 = Wval(mu, logvar, c0, ke0), w01 = Wval(mu, logvar, c0, ke0 + 1);
        float w10 = Wval(mu, logvar, c0, ke1), w11 = Wval(mu, logvar, c0, ke1 + 1);
        float w20 = Wval(mu, logvar, c1, ke0), w21 = Wval(mu, logvar, c1, ke0 + 1);
        float w30 = Wval(mu, logvar, c1, ke1), w31 = Wval(mu, logvar, c1, ke1 + 1);

        uint4 hi, lo;
        hi.x = pack_h2_hi(w00, w01); hi.y = pack_h2_hi(w10, w11);
        hi.z = pack_h2_hi(w20, w21); hi.w = pack_h2_hi(w30, w31);
        lo.x = pack_h2_raw(w00 - fp16_hi(w00), w01 - fp16_hi(w01));
        lo.y = pack_h2_raw(w10 - fp16_hi(w10), w11 - fp16_hi(w11));
        lo.z = pack_h2_raw(w20 - fp16_hi(w20), w21 - fp16_hi(w21));
        lo.w = pack_h2_raw(w30 - fp16_hi(w30), w31 - fp16_hi(w31));

        size_t base = (size_t)(nt * NKT + kt) * W_TILE_U4;
        g_W[base + (nbp * 2 + ks) * 32 + lane] = hi;
        g_W[base + 512 + (nbp * 2 + ks) * 32 + lane] = lo;

    } else {
        int c = blk - PREP_A_BLOCKS - PREP_W_BLOCKS;
        int d = threadIdx.x;
        float lv = logvar[(size_t)c * D_SZ + d];
        float m  = mu[(size_t)c * D_SZ + d];
        float iv = expf(-lv);
        __shared__ float red[256];
        red[d] = fmaf(m * m, iv, lv);
        __syncthreads();
        #pragma unroll
        for (int s = 128; s > 0; s >>= 1) {
            if (d < s) red[d] += red[d + s];
            __syncthreads();
        }
        if (d == 0) {
            const float OFF = -235.24826450039622f - 8.317766166719343f;
            g_constc[c] = fmaf(-0.5f, red[0], OFF);   // folded
        }
    }
}

// ---------------- GEMM: 4 warps x (64x64), 2 CTAs/SM, all-fp16 3-product ----------------
__global__ void __launch_bounds__(NTHREADS, 2)
gemm_hybrid_kernel(float* __restrict__ out) {
    extern __shared__ uint4 smem4[];
    const int tid = threadIdx.x;
    const int lane = tid & 31;
    const int wid = tid >> 5;        // 0..3
    const int wm = wid >> 1;         // 0..1  (64-row band)
    const int wn = wid & 1;          // 0..1  (64-col band)
    const int grp = lane >> 2;
    const int tig = lane & 3;

    const int nt = blockIdx.x;       // 0..31
    const int mt = blockIdx.y;       // 0..127
    const uint32_t sb = smem_u32(smem4);

    const uint4* Abase = g_A + (size_t)mt * NKT * A_TILE_U4;
    const uint4* Wbase = g_W + (size_t)nt * NKT * W_TILE_U4;

    #define LOAD_STAGE(slot, kt)                                               \
    {                                                                          \
        uint32_t s0 = sb + (uint32_t)(slot) * STAGE_BYTES;                     \
        const uint4* ag = Abase + (size_t)(kt) * A_TILE_U4;                    \
        _Pragma("unroll")                                                      \
        for (int c = 0; c < 8; c++) {                                          \
            int id = tid + c * NTHREADS;                                       \
            cp16(s0 + (uint32_t)id * 16, ag + id);                             \
        }                                                                      \
        const uint4* wg = Wbase + (size_t)(kt) * W_TILE_U4;                    \
        uint32_t s1 = s0 + A_TILE_U4 * 16;                                     \
        _Pragma("unroll")                                                      \
        for (int c = 0; c < 8; c++) {                                          \
            int id = tid + c * NTHREADS;                                       \
            cp16(s1 + (uint32_t)id * 16, wg + id);                             \
        }                                                                      \
    }

    float acc[4][8][4];              // [m-frag][n8 group][4]
    #pragma unroll
    for (int i = 0; i < 4; i++)
        #pragma unroll
        for (int j = 0; j < 8; j++)
            #pragma unroll
            for (int q = 0; q < 4; q++) acc[i][j][q] = 0.0f;

    LOAD_STAGE(0, 0) CP_COMMIT();
    LOAD_STAGE(1, 1) CP_COMMIT();

    for (int kt = 0; kt < NKT; kt++) {
        const int slot = kt & 1;
        if (kt == NKT - 1) { CP_WAIT0(); } else { CP_WAIT1(); }   // tail-race fix
        __syncthreads();              // visible to all warps

        const uint4* S   = smem4 + slot * STAGE_U4;
        const uint4* Ahi = S;                     // [mb8][ks2][lane]
        const uint4* Alo = S + 512;
        const uint4* Whi = S + A_TILE_U4;         // [nbp8][ks2][lane]
        const uint4* Wlo = S + A_TILE_U4 + 512;

        #pragma unroll
        for (int s = 0; s < 2; s++) {
            uint4 ah[4], al[4], wh[4], wl[4];
            #pragma unroll
            for (int mf = 0; mf < 4; mf++) {
                ah[mf] = Ahi[((wm * 4 + mf) * 2 + s) * 32 + lane];
                al[mf] = Alo[((wm * 4 + mf) * 2 + s) * 32 + lane];
            }
            #pragma unroll
            for (int p = 0; p < 4; p++) {
                wh[p] = Whi[((wn * 4 + p) * 2 + s) * 32 + lane];
                wl[p] = Wlo[((wn * 4 + p) * 2 + s) * 32 + lane];
            }
            // hi*hi
            #pragma unroll
            for (int mf = 0; mf < 4; mf++)
                #pragma unroll
                for (int p = 0; p < 4; p++) {
                    mma_f16(acc[mf][2 * p],     ah[mf], wh[p].x, wh[p].y);
                    mma_f16(acc[mf][2 * p + 1], ah[mf], wh[p].z, wh[p].w);
                }
            // lo_a*hi_w
            #pragma unroll
            for (int mf = 0; mf < 4; mf++)
                #pragma unroll
                for (int p = 0; p < 4; p++) {
                    mma_f16(acc[mf][2 * p],     al[mf], wh[p].x, wh[p].y);
                    mma_f16(acc[mf][2 * p + 1], al[mf], wh[p].z, wh[p].w);
                }
            // hi_a*lo_w
            #pragma unroll
            for (int mf = 0; mf < 4; mf++)
                #pragma unroll
                for (int p = 0; p < 4; p++) {
                    mma_f16(acc[mf][2 * p],     ah[mf], wl[p].x, wl[p].y);
                    mma_f16(acc[mf][2 * p + 1], ah[mf], wl[p].z, wl[p].w);
                }
        }

        __syncthreads();              // all warps done reading slot
        if (kt + 2 < NKT) {
            LOAD_STAGE(slot, kt + 2)
            CP_COMMIT();
        }
    }

    // ---- epilogue (constc pre-folded with -0.5 and OFF) ----
    const int m0 = mt * BM, n0 = nt * BN;
    #pragma unroll
    for (int mf = 0; mf < 4; mf++) {
        #pragma unroll
        for (int g = 0; g < 8; g++) {
            int row = m0 + wm * 64 + mf * 16 + grp;
            int col = n0 + wn * 64 + g * 8 + tig * 2;
            float c0 = __ldg(g_constc + col);
            float c1 = __ldg(g_constc + col + 1);
            float2 o0, o1;
            o0.x = fmaf(-0.5f, acc[mf][g][0], c0);
            o0.y = fmaf(-0.5f, acc[mf][g][1], c1);
            o1.x = fmaf(-0.5f, acc[mf][g][2], c0);
            o1.y = fmaf(-0.5f, acc[mf][g][3], c1);
            *(float2*)(out + (size_t)row * C_SZ + col)       = o0;
            *(float2*)(out + (size_t)(row + 8) * C_SZ + col) = o1;
        }
    }
}

// ---------------- softmax / argmax: 2 rows per block, shared barriers ----------------
__global__ void __launch_bounds__(256)
softmax_rows_kernel(const float* __restrict__ logits,
                    float* __restrict__ probs,
                    float* __restrict__ pred) {
    // rows processed in reverse (GEMM-tail rows first, possibly L2-warm)
    const int r0 = B_SZ - 2 - 2 * blockIdx.x;      // handles rows r0, r0+1
    const int tid = threadIdx.x;
    const int h = tid >> 7;                         // 0 / 1 -> which row
    const int t = tid & 127;                        // lane within row team
    const int r = r0 + h;

    __shared__ float row[2][C_SZ];
    __shared__ float sm[2][128];
    __shared__ int   si[2][128];
    __shared__ float ss[2][128];

    // load: each team streams its own row (coalesced, float4)
    const float4* src = (const float4*)(logits + (size_t)r * C_SZ);
    #pragma unroll
    for (int k = 0; k < 8; k++)
        ((float4*)row[h])[k * 128 + t] = src[k * 128 + t];
    __syncthreads();

    // max + argmax (first occurrence)
    float m = -INFINITY; int mi = 0;
    #pragma unroll
    for (int k = 0; k < 32; k++) {
        int c = k * 128 + t;
        float v = row[h][c];
        if (v > m) { m = v; mi = c; }
    }
    sm[h][t] = m; si[h][t] = mi;
    __syncthreads();
    #pragma unroll
    for (int s = 64; s > 0; s >>= 1) {
        if (t < s) {
            if (sm[h][t + s] > sm[h][t] ||
                (sm[h][t + s] == sm[h][t] && si[h][t + s] < si[h][t])) {
                sm[h][t] = sm[h][t + s]; si[h][t] = si[h][t + s];
            }
        }
        __syncthreads();
    }
    const float rmax = sm[h][0];
    const int   amax = si[h][0];
    __syncthreads();

    // exp in place + sum (exp once)
    float s = 0.0f;
    #pragma unroll
    for (int k = 0; k < 32; k++) {
        int c = k * 128 + t;
        float e = __expf(row[h][c] - rmax);
        row[h][c] = e;
        s += e;
    }
    ss[h][t] = s;
    __syncthreads();
    #pragma unroll
    for (int st = 64; st > 0; st >>= 1) {
        if (t < st) ss[h][t] += ss[h][t + st];
        __syncthreads();
    }
    const float inv = 1.0f / ss[h][0];

    // scale + streaming write
    float4* dst = (float4*)(probs + (size_t)r * C_SZ);
    #pragma unroll
    for (int k = 0; k < 8; k++) {
        float4 e4 = ((const float4*)row[h])[k * 128 + t];
        e4.x *= inv; e4.y *= inv; e4.z *= inv; e4.w *= inv;
        __stcs(dst + k * 128 + t, e4);
    }
    if (t == 0) pred[r] = (float)amax;
}

// ---------------- launch ----------------
extern "C" void kernel_launch(void* const* d_in, const int* in_sizes, int n_in,
                              void* d_out, int out_size) {
    const float* z      = (const float*)d_in[0];
    const float* mu     = (const float*)d_in[1];
    const float* logvar = (const float*)d_in[2];
    float* out = (float*)d_out;

    float* logits = out;
    float* probs  = out + (size_t)B_SZ * C_SZ;
    float* pred   = out + (size_t)2 * B_SZ * C_SZ;

    cudaFuncSetAttribute(gemm_hybrid_kernel,
                         cudaFuncAttributeMaxDynamicSharedMemorySize, SMEM_BYTES);

    prep_all_kernel<<<PREP_BLOCKS, 256>>>(z, mu, logvar);

    dim3 grid(C_SZ / BN, B_SZ / BM);       // (32, 128)
    gemm_hybrid_kernel<<<grid, NTHREADS, SMEM_BYTES>>>(logits);

    softmax_rows_kernel<<<B_SZ / 2, 256>>>(logits, probs, pred);
}